// round 15
// baseline (speedup 1.0000x reference)
#include <cuda_runtime.h>
#include <cuda_fp16.h>

#define NN 50000
#define EE 800000
#define TEg (EE + NN)          // edges + self loops
#define NEG_SLOPE 0.2f
#define SCAT_BLOCKS ((TEg + 255) / 256)   // 3321
#define GEMM_BLOCKS ((NN + 127) / 128)    // 391 (tensor-core tiles, 128 rows)
#define WSPLIT_BLOCKS 24                  // (64*64 + 32*64) k-pair entries / 256

// -------- static device scratch (no allocations allowed) --------
// g_cnt zero-at-start invariant: statically zeroed; k_scan1 re-zeroes after read.
__device__ __align__(16) __half2 g_h16[NN * 32];   // h in fp16 (gather stream)
__device__ __align__(16) __half2 g_act16[NN * 32]; // layer-1 activated output (fp16)
__device__ float g_as[NN];
__device__ float g_ad[NN];
__device__ int   g_cnt[NN];
__device__ int   g_rowptr[NN + 1];
__device__ int   g_cursor[NN];
__device__ int   g_srcidx[TEg];
__device__ int   g_bsums[128];
// W pre-split to fp16 hi/lo, packed as half2 over k-pairs: [k/2][64]
__device__ __align__(16) unsigned g_w1h[64 * 64];
__device__ __align__(16) unsigned g_w1l[64 * 64];
__device__ __align__(16) unsigned g_w2h[32 * 64];
__device__ __align__(16) unsigned g_w2l[32 * 64];

// fp16 split: x = hi + lo (11+11 mantissa bits ~ 22-bit effective)
__device__ __forceinline__ void split_f16(float x, __half& hi, __half& lo) {
    hi = __float2half_rn(x);
    lo = __float2half_rn(x - __half2float(hi));
}

__device__ __forceinline__ unsigned pack2(__half a, __half b) {
    __half2 t = __halves2half2(a, b);
    return *(unsigned*)&t;
}

__device__ __forceinline__ void mma_f16(float c[4], const unsigned a[4], const unsigned b[2]) {
    asm volatile(
        "mma.sync.aligned.m16n8k16.row.col.f32.f16.f16.f32 "
        "{%0,%1,%2,%3}, {%4,%5,%6,%7}, {%8,%9}, {%0,%1,%2,%3};"
        : "+f"(c[0]), "+f"(c[1]), "+f"(c[2]), "+f"(c[3])
        : "r"(a[0]), "r"(a[1]), "r"(a[2]), "r"(a[3]), "r"(b[0]), "r"(b[1]));
}

// Per-block dtype self-detection (int64 high halves of indices < 50000 are 0)
__device__ __forceinline__ bool detect_is64(const int* e32) {
    int any = __syncthreads_or(e32[2 * threadIdx.x + 1]);
    return any == 0;
}

// ---------------- CSR hist + (fused) weight split/pack ----------------
__global__ __launch_bounds__(256)
void k_hist(const void* __restrict__ ei, const float* __restrict__ W1,
            const float* __restrict__ W2) {
    if ((int)blockIdx.x >= SCAT_BLOCKS) {
        int idx = ((int)blockIdx.x - SCAT_BLOCKS) * 256 + threadIdx.x;
        const float* W; unsigned *Wh, *Wl; int j;
        if (idx < 64 * 64) { W = W1; Wh = g_w1h; Wl = g_w1l; j = idx; }
        else { W = W2; Wh = g_w2h; Wl = g_w2l; j = idx - 64 * 64; }   // j < 32*64
        int kp = j >> 6, n = j & 63;
        float x0 = W[(size_t)(2 * kp) * 64 + n];
        float x1 = W[(size_t)(2 * kp + 1) * 64 + n];
        __half h0, l0, h1, l1;
        split_f16(x0, h0, l0);
        split_f16(x1, h1, l1);
        Wh[j] = pack2(h0, h1);
        Wl[j] = pack2(l0, l1);
        return;
    }
    const int* e32 = (const int*)ei;
    bool is64 = detect_is64(e32);
    int i = blockIdx.x * 256 + threadIdx.x;
    if (i >= TEg) return;
    int d;
    if (i < EE)
        d = is64 ? (int)((const long long*)ei)[(long long)EE + i] : e32[EE + i];
    else
        d = i - EE;
    if ((unsigned)d < NN) atomicAdd(&g_cnt[d], 1);
}

// block-level inclusive scan (shfl-based); zeroes g_cnt after read
__global__ void k_scan1() {
    __shared__ int wsum[16];
    int t = threadIdx.x;
    int lane = t & 31, wid = t >> 5;
    int i = blockIdx.x * 512 + t;
    int v = 0;
    if (i < NN) { v = g_cnt[i]; g_cnt[i] = 0; }

    int s = v;
    #pragma unroll
    for (int off = 1; off < 32; off <<= 1) {
        int n = __shfl_up_sync(0xffffffffu, s, off);
        if (lane >= off) s += n;
    }
    if (lane == 31) wsum[wid] = s;
    __syncthreads();
    if (wid == 0) {
        int ws = (lane < 16) ? wsum[lane] : 0;
        #pragma unroll
        for (int off = 1; off < 16; off <<= 1) {
            int n = __shfl_up_sync(0xffffffffu, ws, off);
            if (lane >= off) ws += n;
        }
        if (lane < 16) wsum[lane] = ws;
    }
    __syncthreads();
    int base = (wid > 0) ? wsum[wid - 1] : 0;
    s += base;
    if (i < NN) g_rowptr[i + 1] = s;
    if (t == 511) g_bsums[blockIdx.x] = s;
}

__global__ __launch_bounds__(256) void k_scan3(int nblocks) {
    __shared__ int boff[128];
    __shared__ int wtot[4];
    int t = threadIdx.x;
    if (t < 128) {
        int lane = t & 31, wd = t >> 5;
        int v = (t < nblocks) ? g_bsums[t] : 0;
        int s = v;
        #pragma unroll
        for (int off = 1; off < 32; off <<= 1) {
            int n = __shfl_up_sync(0xffffffffu, s, off);
            if (lane >= off) s += n;
        }
        boff[t] = s;
        if (lane == 31) wtot[wd] = s;
    }
    __syncthreads();
    if (t < 128) {
        int wd = t >> 5;
        int add = 0;
        #pragma unroll
        for (int j = 0; j < 3; ++j)
            if (j < wd) add += wtot[j];
        boff[t] += add;
    }
    __syncthreads();
    int i = blockIdx.x * 256 + t;
    if (i == 0) { g_rowptr[0] = 0; g_cursor[0] = 0; }
    if (i < NN) {
        int blk = i >> 9;
        int off = (blk > 0) ? boff[blk - 1] : 0;
        int v = g_rowptr[i + 1] + off;
        g_rowptr[i + 1] = v;
        if (i + 1 < NN) g_cursor[i + 1] = v;
    }
}

// ---------------- tensor-core GEMM tile (A fp16, B 2-way split) ------------
// Single load phase: whole A tile (128 x FIN) + whole B into dynamic smem,
// one __syncthreads, then the full MMA mainloop with no further syncs.
// Block 256 thr = 8 warps (4 M x 2 N); warp tile 32x32.
// smem layout (unsigned words):
//   A:  [128][AS]  AS = FIN/2 + 4  (stride ≡ 4 mod 32 → conflict-free frags)
//   Bh: [KP][72], Bl: [KP][72]     KP = FIN/2 (stride 72 → conflict-free)
//   sp: 512 floats (projection scratch)
template <int FIN, bool USE_ACT, bool LAYER1>
__device__ __forceinline__
void gemm_tc(int bid, const float* __restrict__ Xext,
             const float* __restrict__ a_src, const float* __restrict__ a_dst) {
    extern __shared__ unsigned sm[];
    constexpr int AS = FIN / 2 + 4;
    constexpr int KP = FIN / 2;
    constexpr int BS = 72;
    constexpr int OFF_BH = 128 * AS;
    constexpr int OFF_BL = OFF_BH + KP * BS;
    constexpr int OFF_SP = OFF_BL + KP * BS;
    float* sp_s = (float*)(sm + OFF_SP);        // [2][128]
    float* sp_d = (float*)(sm + OFF_SP + 256);  // [2][128]

    const unsigned* WhG = LAYER1 ? g_w1h : g_w2h;
    const unsigned* WlG = LAYER1 ? g_w1l : g_w2l;

    int tid = threadIdx.x;
    int lane = tid & 31, wid = tid >> 5;
    int wm = wid >> 1, wn = wid & 1;
    int g = lane >> 2, tig = lane & 3;
    int row0 = bid * 128;

    // ---- load whole A tile ----
    if (USE_ACT) {
        // fp16 act: 128 rows x 8 uint4 = 1024 uint4, 4/thread
        #pragma unroll
        for (int l = 0; l < 4; ++l) {
            int idx = l * 256 + tid;
            int r = idx >> 3, q4 = idx & 7;
            int row = row0 + r;
            uint4 v = make_uint4(0u, 0u, 0u, 0u);
            if (row < NN)
                v = *(const uint4*)((const unsigned*)g_act16 + (size_t)row * 32 + q4 * 4);
            *(uint4*)(sm + r * AS + q4 * 4) = v;
        }
    } else {
        // fp32 X: 128 rows x FIN/4 float4; convert to half2 pairs
        constexpr int NF4 = 128 * (FIN / 4);
        #pragma unroll
        for (int l = 0; l < NF4 / 256; ++l) {
            int idx = l * 256 + tid;
            int r = idx / (FIN / 4), q = idx % (FIN / 4);
            int row = row0 + r;
            float4 v = make_float4(0.f, 0.f, 0.f, 0.f);
            if (row < NN) v = *(const float4*)(Xext + (size_t)row * FIN + q * 4);
            __half2 p0 = __floats2half2_rn(v.x, v.y);
            __half2 p1 = __floats2half2_rn(v.z, v.w);
            *(uint2*)(sm + r * AS + q * 2) = make_uint2(*(unsigned*)&p0, *(unsigned*)&p1);
        }
    }
    // ---- load whole B (pre-split hi/lo) ----
    {
        constexpr int NB4 = KP * 16;       // uint4 count per half
        #pragma unroll
        for (int l = 0; l < NB4 / 256; ++l) {
            int idx = l * 256 + tid;
            int k = idx >> 4, c4 = idx & 15;
            uint4 vh = *(const uint4*)(WhG + (size_t)k * 64 + c4 * 4);
            uint4 vl = *(const uint4*)(WlG + (size_t)k * 64 + c4 * 4);
            *(uint4*)(sm + OFF_BH + k * BS + c4 * 4) = vh;
            *(uint4*)(sm + OFF_BL + k * BS + c4 * 4) = vl;
        }
    }
    __syncthreads();

    // ---- mainloop: all data in smem, no syncs ----
    float acc[2][4][4] = {};
    #pragma unroll
    for (int kc = 0; kc < FIN / 32; ++kc) {
        #pragma unroll
        for (int ks = 0; ks < 2; ++ks) {
            int kp0 = kc * 16 + ks * 8;
            unsigned bh[4][2], bl[4][2];
            #pragma unroll
            for (int nt = 0; nt < 4; ++nt) {
                int c = wn * 32 + nt * 8 + g;
                bh[nt][0] = sm[OFF_BH + (kp0 + tig) * BS + c];
                bh[nt][1] = sm[OFF_BH + (kp0 + tig + 4) * BS + c];
                bl[nt][0] = sm[OFF_BL + (kp0 + tig) * BS + c];
                bl[nt][1] = sm[OFF_BL + (kp0 + tig + 4) * BS + c];
            }
            #pragma unroll
            for (int mt = 0; mt < 2; ++mt) {
                int rb = wm * 32 + mt * 16;
                unsigned ah[4];
                ah[0] = sm[(rb + g) * AS + kp0 + tig];
                ah[1] = sm[(rb + g + 8) * AS + kp0 + tig];
                ah[2] = sm[(rb + g) * AS + kp0 + tig + 4];
                ah[3] = sm[(rb + g + 8) * AS + kp0 + tig + 4];
                #pragma unroll
                for (int nt = 0; nt < 4; ++nt) {
                    mma_f16(acc[mt][nt], ah, bh[nt]);
                    mma_f16(acc[mt][nt], ah, bl[nt]);
                }
            }
        }
    }

    // H store (fp16): one half2 per frag row (c even: c/2 = wn*16 + nt*4 + tig)
    #pragma unroll
    for (int mt = 0; mt < 2; ++mt)
        #pragma unroll
        for (int nt = 0; nt < 4; ++nt) {
            int r = row0 + wm * 32 + mt * 16 + g;
            int ch = wn * 16 + nt * 4 + tig;
            if (r < NN)
                g_h16[(size_t)r * 32 + ch] = __floats2half2_rn(acc[mt][nt][0], acc[mt][nt][1]);
            if (r + 8 < NN)
                g_h16[(size_t)(r + 8) * 32 + ch] = __floats2half2_rn(acc[mt][nt][2], acc[mt][nt][3]);
        }

    // attention projections from fp32 accumulators
    float asv[4][2], adv[4][2];
    #pragma unroll
    for (int nt = 0; nt < 4; ++nt) {
        int c = wn * 32 + nt * 8 + 2 * tig;
        asv[nt][0] = a_src[c]; asv[nt][1] = a_src[c + 1];
        adv[nt][0] = a_dst[c]; adv[nt][1] = a_dst[c + 1];
    }
    #pragma unroll
    for (int mt = 0; mt < 2; ++mt) {
        float s0 = 0.f, s1 = 0.f, d0 = 0.f, d1 = 0.f;
        #pragma unroll
        for (int nt = 0; nt < 4; ++nt) {
            s0 = fmaf(acc[mt][nt][0], asv[nt][0], fmaf(acc[mt][nt][1], asv[nt][1], s0));
            s1 = fmaf(acc[mt][nt][2], asv[nt][0], fmaf(acc[mt][nt][3], asv[nt][1], s1));
            d0 = fmaf(acc[mt][nt][0], adv[nt][0], fmaf(acc[mt][nt][1], adv[nt][1], d0));
            d1 = fmaf(acc[mt][nt][2], adv[nt][0], fmaf(acc[mt][nt][3], adv[nt][1], d1));
        }
        s0 += __shfl_xor_sync(0xffffffffu, s0, 1); s0 += __shfl_xor_sync(0xffffffffu, s0, 2);
        s1 += __shfl_xor_sync(0xffffffffu, s1, 1); s1 += __shfl_xor_sync(0xffffffffu, s1, 2);
        d0 += __shfl_xor_sync(0xffffffffu, d0, 1); d0 += __shfl_xor_sync(0xffffffffu, d0, 2);
        d1 += __shfl_xor_sync(0xffffffffu, d1, 1); d1 += __shfl_xor_sync(0xffffffffu, d1, 2);
        if (tig == 0) {
            int rl = wm * 32 + mt * 16 + g;
            sp_s[wn * 128 + rl] = s0; sp_s[wn * 128 + rl + 8] = s1;
            sp_d[wn * 128 + rl] = d0; sp_d[wn * 128 + rl + 8] = d1;
        }
    }
    __syncthreads();
    if (tid < 128) {
        int r = row0 + tid;
        if (r < NN) {
            g_as[r] = sp_s[tid] + sp_s[128 + tid];
            g_ad[r] = sp_d[tid] + sp_d[128 + tid];
        }
    }
}

// smem sizes (bytes)
#define SMEM_L1 ((128 * 68 + 2 * 64 * 72 + 512) * 4)   // 73728
#define SMEM_L2 ((128 * 36 + 2 * 32 * 72 + 512) * 4)   // 38912

// Fused layer-1: gemm blocks first, then scatter.
__global__ __launch_bounds__(256)
void k_fused1(const float* __restrict__ X,
              const float* __restrict__ a_src, const float* __restrict__ a_dst,
              const void* __restrict__ ei) {
    if ((int)blockIdx.x < GEMM_BLOCKS) {
        gemm_tc<128, false, true>(blockIdx.x, X, a_src, a_dst);
        return;
    }
    const int* e32 = (const int*)ei;
    bool is64 = detect_is64(e32);
    int i = ((int)blockIdx.x - GEMM_BLOCKS) * 256 + threadIdx.x;
    if (i >= TEg) return;
    int s, d;
    if (i < EE) {
        if (is64) {
            s = (int)((const long long*)ei)[i];
            d = (int)((const long long*)ei)[(long long)EE + i];
        } else {
            s = e32[i];
            d = e32[EE + i];
        }
    } else { s = i - EE; d = s; }
    if ((unsigned)d >= NN || (unsigned)s >= NN) return;
    int pos = atomicAdd(&g_cursor[d], 1);
    if ((unsigned)pos < TEg) g_srcidx[pos] = s;
}

__global__ __launch_bounds__(256)
void k_gemm2(const float* __restrict__ a_src, const float* __restrict__ a_dst) {
    gemm_tc<64, true, false>(blockIdx.x, nullptr, a_src, a_dst);
}

// ---------------- single-pass online-softmax aggregation ----------------
// One warp per destination node; lane owns features {2*lane, 2*lane+1}.
template <bool WRITE_ACT>
__global__ __launch_bounds__(256)
void k_agg(const float* __restrict__ bias, float* __restrict__ OUText, int do_relu) {
    int w = (blockIdx.x * blockDim.x + threadIdx.x) >> 5;
    int lane = threadIdx.x & 31;
    if (w >= NN) return;

    int beg = g_rowptr[w], end = g_rowptr[w + 1];
    float adv = g_ad[w];

    float m = -1e30f;
    float acc0 = 0.f, acc1 = 0.f, denom = 0.f;

    for (int base = beg; base < end; base += 32) {
        int i = base + lane;
        float e = -1e30f;
        int s = 0;
        if (i < end) {
            s = g_srcidx[i];
            float t = g_as[s] + adv;
            e = (t > 0.f) ? t : NEG_SLOPE * t;
        }
        float bm = e;
        #pragma unroll
        for (int off = 16; off; off >>= 1)
            bm = fmaxf(bm, __shfl_xor_sync(0xffffffffu, bm, off));
        float mnew = fmaxf(m, bm);
        float scale = __expf(m - mnew);
        acc0 *= scale; acc1 *= scale; denom *= scale;
        m = mnew;

        float wgt = (i < end) ? __expf(e - mnew) : 0.f;
        denom += wgt;

        int cnt = end - base; if (cnt > 32) cnt = 32;
        int cnt4 = (cnt + 3) & ~3;
        for (int j = 0; j < cnt4; j += 4) {
            float wj0 = __shfl_sync(0xffffffffu, wgt, j);
            float wj1 = __shfl_sync(0xffffffffu, wgt, j + 1);
            float wj2 = __shfl_sync(0xffffffffu, wgt, j + 2);
            float wj3 = __shfl_sync(0xffffffffu, wgt, j + 3);
            int sj0 = __shfl_sync(0xffffffffu, s, j);
            int sj1 = __shfl_sync(0xffffffffu, s, j + 1);
            int sj2 = __shfl_sync(0xffffffffu, s, j + 2);
            int sj3 = __shfl_sync(0xffffffffu, s, j + 3);
            float2 f0 = __half22float2(g_h16[(size_t)sj0 * 32 + lane]);
            float2 f1 = __half22float2(g_h16[(size_t)sj1 * 32 + lane]);
            float2 f2 = __half22float2(g_h16[(size_t)sj2 * 32 + lane]);
            float2 f3 = __half22float2(g_h16[(size_t)sj3 * 32 + lane]);
            acc0 = fmaf(wj0, f0.x, acc0); acc1 = fmaf(wj0, f0.y, acc1);
            acc0 = fmaf(wj1, f1.x, acc0); acc1 = fmaf(wj1, f1.y, acc1);
            acc0 = fmaf(wj2, f2.x, acc0); acc1 = fmaf(wj2, f2.y, acc1);
            acc0 = fmaf(wj3, f3.x, acc0); acc1 = fmaf(wj3, f3.y, acc1);
        }
    }
    #pragma unroll
    for (int off = 16; off; off >>= 1)
        denom += __shfl_xor_sync(0xffffffffu, denom, off);

    float inv = 1.f / denom;
    float o0 = fmaf(acc0, inv, bias[2 * lane]);
    float o1 = fmaf(acc1, inv, bias[2 * lane + 1]);
    if (do_relu) { o0 = fmaxf(o0, 0.f); o1 = fmaxf(o1, 0.f); }
    if (WRITE_ACT) {
        g_act16[(size_t)w * 32 + lane] = __floats2half2_rn(o0, o1);
    } else {
        *(float2*)(OUText + (size_t)w * 64 + 2 * lane) = make_float2(o0, o1);
    }
}

// ---------------- launch ----------------
extern "C" void kernel_launch(void* const* d_in, const int* in_sizes, int n_in,
                              void* d_out, int out_size) {
    const float* x   = (const float*)d_in[0];
    const void*  ei  = d_in[1];                 // int32 or int64 — self-detected
    const float* W1  = (const float*)d_in[2];
    const float* a1s = (const float*)d_in[3];
    const float* a1d = (const float*)d_in[4];
    const float* b1  = (const float*)d_in[5];
    const float* W2  = (const float*)d_in[6];
    const float* a2s = (const float*)d_in[7];
    const float* a2d = (const float*)d_in[8];
    const float* b2  = (const float*)d_in[9];
    float* out = (float*)d_out;

    const int SCAN_BLOCKS = (NN + 511) / 512;   // 98
    const int WARP_GRID   = (NN * 32 + 255) / 256;

    // allow 72KB dynamic smem for the layer-1 GEMM (host-side attribute; no alloc)
    cudaFuncSetAttribute(k_fused1, cudaFuncAttributeMaxDynamicSharedMemorySize, SMEM_L1);

    // hist (+ fused W fp16 split/pack) → scan → scan-combine
    k_hist  <<<SCAT_BLOCKS + WSPLIT_BLOCKS, 256>>>(ei, W1, W2);
    k_scan1 <<<SCAN_BLOCKS, 512>>>();
    k_scan3 <<<(NN + 255) / 256, 256>>>(SCAN_BLOCKS);

    // layer 1: tensor-core GEMM1 fused with CSR scatter
    k_fused1<<<GEMM_BLOCKS + SCAT_BLOCKS, 256, SMEM_L1>>>(x, a1s, a1d, ei);
    k_agg<true> <<<WARP_GRID, 256>>>(b1, out /*unused*/, 1);

    // layer 2
    k_gemm2 <<<GEMM_BLOCKS, 256, SMEM_L2>>>(a2s, a2d);
    k_agg<false><<<WARP_GRID, 256>>>(b2, out, 0);
}